// round 12
// baseline (speedup 1.0000x reference)
#include <cuda_runtime.h>
#include <math_constants.h>

// GraphPoolMol: masked neighborhood max-pool over graph Laplacian sparsity.
// B=64, MAX_ATOM=128, N_FEAT=128.
// out[b,i,f] = max_{j: L[b,i,j]!=0, j<n, i<n} x[b,j,f]; 0 if i>=n.
// diag(L)=1 => for i<n the mask contains j=i (cnt>=1), so the reference's
// "no neighbor" fallback never fires for valid rows, and repeating a valid
// neighbor in the gather never changes the max.
//
// Design: block = 32 rows of one batch, 512 threads (16 warps x 2 rows).
// x[b] (64 KB) arrives via one cp.async.bulk overlapped with the L-row /
// ballot / index-extraction prologue; the gather then runs out of shared
// memory (29-cyc LDS) with MLP-4 batches. 3 blocks/SM -> 48 warps/SM.

#define AT 128
#define NF 128
#define THREADS 512
#define X_BYTES (AT * NF * 4)   // 64 KB

__device__ __forceinline__ float4 fmax4(float4 a, float4 b) {
    return make_float4(fmaxf(a.x, b.x), fmaxf(a.y, b.y),
                       fmaxf(a.z, b.z), fmaxf(a.w, b.w));
}

// Position of the r-th (0-indexed) set bit of m; in-range garbage when
// r >= popc(m) (those lanes are never consumed).
__device__ __forceinline__ int nth_bit(unsigned m, int r) {
    int j = 0, c;
    c = __popc(m & 0xFFFFu); if (r >= c) { r -= c; m >>= 16; j = 16; }
    c = __popc(m & 0xFFu);   if (r >= c) { r -= c; m >>= 8;  j += 8; }
    c = __popc(m & 0xFu);    if (r >= c) { r -= c; m >>= 4;  j += 4; }
    c = __popc(m & 0x3u);    if (r >= c) { r -= c; m >>= 2;  j += 2; }
    c = (int)(m & 1u);       if (r >= c) {                   j += 1; }
    return j;
}

// Masked max over one row from the SMEM x tile, given the warp-uniform
// 128-bit column mask (ballot word q: col = 4*bit + q). Requires cnt >= 1.
__device__ __forceinline__ float4 pool_row_smem(const float4* __restrict__ xs4,
                                                int lane,
                                                unsigned m0, unsigned m1,
                                                unsigned m2, unsigned m3)
{
    const int c0 = __popc(m0), c1 = __popc(m1), c2 = __popc(m2);
    const int cnt = c0 + c1 + c2 + __popc(m3);

    float4 acc0 = make_float4(-CUDART_INF_F, -CUDART_INF_F,
                              -CUDART_INF_F, -CUDART_INF_F);
    float4 acc1 = acc0;

    int done = 0;
    while (done < cnt) {                        // one pass unless cnt > 32
        int t = done + lane;
        unsigned m = m0; int q = 0;
        if (t >= c0) { t -= c0; m = m1; q = 1;
            if (t >= c1) { t -= c1; m = m2; q = 2;
                if (t >= c2) { t -= c2; m = m3; q = 3; } } }
        const int jmine = 4 * nth_bit(m, min(t, 31)) + q;   // in [0,127]

        const int cm = min(cnt - done, 32);
        for (int kb = 0; kb < cm; kb += 4) {
            // Clamped source lane pads by repeating the last valid neighbor
            // (harmless for max).
            const int j0 = __shfl_sync(0xffffffffu, jmine, min(kb + 0, cm - 1));
            const int j1 = __shfl_sync(0xffffffffu, jmine, min(kb + 1, cm - 1));
            const int j2 = __shfl_sync(0xffffffffu, jmine, min(kb + 2, cm - 1));
            const int j3 = __shfl_sync(0xffffffffu, jmine, min(kb + 3, cm - 1));
            const float4 v0 = xs4[j0 * 32 + lane];
            const float4 v1 = xs4[j1 * 32 + lane];
            const float4 v2 = xs4[j2 * 32 + lane];
            const float4 v3 = xs4[j3 * 32 + lane];
            acc0 = fmax4(acc0, v0);
            acc1 = fmax4(acc1, v1);
            acc0 = fmax4(acc0, v2);
            acc1 = fmax4(acc1, v3);
        }
        done += cm;
    }
    return fmax4(acc0, acc1);
}

__global__ __launch_bounds__(THREADS, 3)
void graph_pool_mol_kernel(const float* __restrict__ xg,
                           const float* __restrict__ Lg,
                           const int* __restrict__ mol_slice,
                           float* __restrict__ outg)
{
    const int b    = blockIdx.x >> 2;
    const int base = (blockIdx.x & 3) * 32;
    const int tid  = threadIdx.x;
    const int wid  = tid >> 5;
    const int lane = tid & 31;
    const int i0   = base + 2 * wid;
    const int i1   = i0 + 1;

    extern __shared__ float xs[];               // 64 KB x tile
    __shared__ __align__(8) unsigned long long mbar;
    const unsigned mbar_s = (unsigned)__cvta_generic_to_shared(&mbar);

    if (tid == 0) {
        asm volatile("mbarrier.init.shared.b64 [%0], %1;"
                     :: "r"(mbar_s), "r"(1) : "memory");
    }

    // Issue all long-latency loads before anything depends on them.
    const int n = __ldg(mol_slice + 2 * b);     // mol_slice[b,0] = n_atoms
    const float4* Lb4 = reinterpret_cast<const float4*>(Lg + (size_t)b * AT * AT);
    const float4 L0 = __ldg(Lb4 + (size_t)i0 * 32 + lane);
    const float4 L1 = __ldg(Lb4 + (size_t)i1 * 32 + lane);

    __syncthreads();                            // mbar init visible

    if (tid == 0 && base < n) {                 // active block: stage x[b]
        asm volatile("mbarrier.arrive.expect_tx.shared.b64 _, [%0], %1;"
                     :: "r"(mbar_s), "r"(X_BYTES) : "memory");
        const unsigned xs_s = (unsigned)__cvta_generic_to_shared(xs);
        asm volatile(
            "cp.async.bulk.shared::cta.global.mbarrier::complete_tx::bytes "
            "[%0], [%1], %2, [%3];"
            :: "r"(xs_s), "l"(xg + (size_t)b * AT * NF), "r"(X_BYTES),
               "r"(mbar_s) : "memory");
    }

    float4* outb = reinterpret_cast<float4*>(outg) + (size_t)b * AT * 32;
    const float4 zero = make_float4(0.f, 0.f, 0.f, 0.f);

    if (i0 >= n) {                              // both rows padded
        outb[(size_t)i0 * 32 + lane] = zero;
        outb[(size_t)i1 * 32 + lane] = zero;
        return;                                 // valid warps keep block alive
    }
    const bool v1 = (i1 < n);                   // warp-uniform

    // ---- Ballot masks for both rows (word q: col = 4*bit + q) -------------
    const int j0c = 4 * lane;
    const bool c0v = (j0c + 0) < n, c1v = (j0c + 1) < n,
               c2v = (j0c + 2) < n, c3v = (j0c + 3) < n;

    const unsigned a0 = __ballot_sync(0xffffffffu, (L0.x != 0.f) && c0v);
    const unsigned a1 = __ballot_sync(0xffffffffu, (L0.y != 0.f) && c1v);
    const unsigned a2 = __ballot_sync(0xffffffffu, (L0.z != 0.f) && c2v);
    const unsigned a3 = __ballot_sync(0xffffffffu, (L0.w != 0.f) && c3v);
    const unsigned b0 = __ballot_sync(0xffffffffu, v1 && (L1.x != 0.f) && c0v);
    const unsigned b1 = __ballot_sync(0xffffffffu, v1 && (L1.y != 0.f) && c1v);
    const unsigned b2 = __ballot_sync(0xffffffffu, v1 && (L1.z != 0.f) && c2v);
    const unsigned b3 = __ballot_sync(0xffffffffu, v1 && (L1.w != 0.f) && c3v);

    // ---- Wait for the staged x tile ----------------------------------------
    {
        unsigned done;
        asm volatile(
            "{\n\t"
            ".reg .pred p;\n\t"
            "mbarrier.try_wait.parity.acquire.cta.shared::cta.b64 p, [%1], %2;\n\t"
            "selp.b32 %0, 1, 0, p;\n\t"
            "}"
            : "=r"(done) : "r"(mbar_s), "r"(0) : "memory");
        if (!done) {
            asm volatile(
                "{\n\t"
                ".reg .pred P1;\n\t"
                "W_%=:\n\t"
                "mbarrier.try_wait.parity.acquire.cta.shared::cta.b64 P1, [%0], %1, 0x989680;\n\t"
                "@P1 bra.uni D_%=;\n\t"
                "bra.uni W_%=;\n\t"
                "D_%=:\n\t"
                "}"
                :: "r"(mbar_s), "r"(0) : "memory");
        }
    }

    // ---- Gather both rows from the SMEM tile --------------------------------
    const float4* xs4 = reinterpret_cast<const float4*>(xs);
    outb[(size_t)i0 * 32 + lane] = pool_row_smem(xs4, lane, a0, a1, a2, a3);
    outb[(size_t)i1 * 32 + lane] = v1 ? pool_row_smem(xs4, lane, b0, b1, b2, b3)
                                      : zero;
}

extern "C" void kernel_launch(void* const* d_in, const int* in_sizes, int n_in,
                              void* d_out, int out_size)
{
    const float* node_features = (const float*)d_in[0];
    const float* laplacian     = (const float*)d_in[1];
    const int*   mol_slice     = (const int*)d_in[2];
    // d_in[3] = l_slice (unused)

    float* out = (float*)d_out;

    cudaFuncSetAttribute(graph_pool_mol_kernel,
                         cudaFuncAttributeMaxDynamicSharedMemorySize, X_BYTES);

    const int B = 64;
    graph_pool_mol_kernel<<<B * 4, THREADS, X_BYTES>>>(
        node_features, laplacian, mol_slice, out);
}

// round 13
// speedup vs baseline: 1.1882x; 1.1882x over previous
#include <cuda_runtime.h>
#include <math_constants.h>

// GraphPoolMol: masked neighborhood max-pool over graph Laplacian sparsity.
// B=64, MAX_ATOM=128, N_FEAT=128.
// out[b,i,f] = max_{j: L[b,i,j]!=0, j<n, i<n} x[b,j,f]; 0 if i>=n.
// diag(L)=1 => for i<n the mask contains j=i (cnt>=1), so the reference's
// "no neighbor" fallback never fires for valid rows, and repeating a valid
// neighbor in a gather batch never changes the max.
//
// Warp-per-row, no smem/barriers. 256-thread blocks (8 rows of one batch),
// grid=1024, __launch_bounds__(256,6) -> 48 warps/SM target occupancy.
// MLP-4 float4 gather batches keep regs <= 42.

#define AT 128
#define NF 128
#define THREADS 256

__device__ __forceinline__ float4 fmax4(float4 a, float4 b) {
    return make_float4(fmaxf(a.x, b.x), fmaxf(a.y, b.y),
                       fmaxf(a.z, b.z), fmaxf(a.w, b.w));
}

// Position of the r-th (0-indexed) set bit of m; in-range garbage when
// r >= popc(m) (those lanes are never consumed).
__device__ __forceinline__ int nth_bit(unsigned m, int r) {
    int j = 0, c;
    c = __popc(m & 0xFFFFu); if (r >= c) { r -= c; m >>= 16; j = 16; }
    c = __popc(m & 0xFFu);   if (r >= c) { r -= c; m >>= 8;  j += 8; }
    c = __popc(m & 0xFu);    if (r >= c) { r -= c; m >>= 4;  j += 4; }
    c = __popc(m & 0x3u);    if (r >= c) { r -= c; m >>= 2;  j += 2; }
    c = (int)(m & 1u);       if (r >= c) {                   j += 1; }
    return j;
}

__global__ __launch_bounds__(THREADS, 6)
void graph_pool_mol_kernel(const float* __restrict__ xg,
                           const float* __restrict__ Lg,
                           const int* __restrict__ mol_slice,
                           float* __restrict__ outg)
{
    const int b    = blockIdx.x >> 4;              // batch (16 blocks each)
    const int i    = ((blockIdx.x & 15) << 3) + (threadIdx.x >> 5); // row
    const int lane = threadIdx.x & 31;

    // Issue both long-latency loads before anything depends on either.
    const int n = __ldg(mol_slice + 2 * b);        // mol_slice[b,0] = n_atoms
    const float4 Lv = __ldg(reinterpret_cast<const float4*>(
                                Lg + ((size_t)b * AT + i) * AT) + lane);

    float4* outr = reinterpret_cast<float4*>(outg) + ((size_t)b * AT + i) * 32;

    if (i >= n) {                                  // padded row
        outr[lane] = make_float4(0.f, 0.f, 0.f, 0.f);
        return;
    }

    // ---- Warp-uniform 128-bit mask (ballot word q: col = 4*bit + q) -------
    const int j0 = 4 * lane;
    const unsigned m0 = __ballot_sync(0xffffffffu, (Lv.x != 0.f) && (j0 + 0 < n));
    const unsigned m1 = __ballot_sync(0xffffffffu, (Lv.y != 0.f) && (j0 + 1 < n));
    const unsigned m2 = __ballot_sync(0xffffffffu, (Lv.z != 0.f) && (j0 + 2 < n));
    const unsigned m3 = __ballot_sync(0xffffffffu, (Lv.w != 0.f) && (j0 + 3 < n));

    const int c0 = __popc(m0), c1 = __popc(m1), c2 = __popc(m2);
    const int cnt = c0 + c1 + c2 + __popc(m3);     // >= 1 (diagonal)

    const float4* xb = reinterpret_cast<const float4*>(xg + (size_t)b * AT * NF);
    float4 acc0 = make_float4(-CUDART_INF_F, -CUDART_INF_F,
                              -CUDART_INF_F, -CUDART_INF_F);
    float4 acc1 = acc0;

    int done = 0;
    while (done < cnt) {                           // one pass unless cnt > 32
        // Lane s extracts the (done+s)-th set column.
        int t = done + lane;
        unsigned m = m0; int q = 0;
        if (t >= c0) { t -= c0; m = m1; q = 1;
            if (t >= c1) { t -= c1; m = m2; q = 2;
                if (t >= c2) { t -= c2; m = m3; q = 3; } } }
        const int jmine = 4 * nth_bit(m, min(t, 31)) + q;   // in [0,127]

        const int cm = min(cnt - done, 32);
        for (int kb = 0; kb < cm; kb += 4) {
            // Clamped source lane repeats the last valid neighbor (harmless).
            const int ja = __shfl_sync(0xffffffffu, jmine, min(kb + 0, cm - 1));
            const int jb = __shfl_sync(0xffffffffu, jmine, min(kb + 1, cm - 1));
            const int jc = __shfl_sync(0xffffffffu, jmine, min(kb + 2, cm - 1));
            const int jd = __shfl_sync(0xffffffffu, jmine, min(kb + 3, cm - 1));
            const float4 va = __ldg(xb + ja * 32 + lane);
            const float4 vb = __ldg(xb + jb * 32 + lane);
            const float4 vc = __ldg(xb + jc * 32 + lane);
            const float4 vd = __ldg(xb + jd * 32 + lane);
            acc0 = fmax4(acc0, va);
            acc1 = fmax4(acc1, vb);
            acc0 = fmax4(acc0, vc);
            acc1 = fmax4(acc1, vd);
        }
        done += cm;
    }

    outr[lane] = fmax4(acc0, acc1);
}

extern "C" void kernel_launch(void* const* d_in, const int* in_sizes, int n_in,
                              void* d_out, int out_size)
{
    const float* node_features = (const float*)d_in[0];
    const float* laplacian     = (const float*)d_in[1];
    const int*   mol_slice     = (const int*)d_in[2];
    // d_in[3] = l_slice (unused)

    float* out = (float*)d_out;

    const int B = 64;
    const int blocks = B * (AT / 8);               // 1024 blocks, 8 rows each
    graph_pool_mol_kernel<<<blocks, THREADS>>>(
        node_features, laplacian, mol_slice, out);
}